// round 1
// baseline (speedup 1.0000x reference)
#include <cuda_runtime.h>
#include <math.h>

#define NROWS 8192
#define DDIM  128
#define KNEG  100
#define INV_TEMP (1.0f/0.07f)

// ---------------- scratch (device globals: allowed) ----------------
__device__ float g_x1t[NROWS * DDIM];              // transposed x1 (8192 x 128)
__device__ float g_x2t[NROWS * DDIM];              // transposed x2
__device__ float g_sq [NROWS];                     // |x1_i|^2
__device__ float g_invn[NROWS];                    // 1/|x1_i|
__device__ float g_pos[NROWS];                     // positive sums
__device__ float g_dot[(size_t)NROWS * NROWS];     // Gram matrix (256 MB)
__device__ float g_loss[NROWS];

// ---------------- K0: transpose (b,d,h,w) -> (b*h*w, d) ----------------
__global__ void transpose_kernel(const float* __restrict__ x, int which) {
    __shared__ float tile[32][33];
    float* xt = which ? g_x2t : g_x1t;
    int b = blockIdx.z, dt = blockIdx.y, pt = blockIdx.x;
    int tx = threadIdx.x, ty = threadIdx.y;            // 32 x 8
    const float* src = x + (size_t)b * 131072 + (size_t)(dt * 32) * 1024 + pt * 32;
    #pragma unroll
    for (int r = ty; r < 32; r += 8)
        tile[r][tx] = src[(size_t)r * 1024 + tx];      // tile[d_local][pix_local]
    __syncthreads();
    float* dst = xt + (size_t)(b * 1024 + pt * 32) * DDIM + dt * 32;
    #pragma unroll
    for (int r = ty; r < 32; r += 8)
        dst[(size_t)r * DDIM + tx] = tile[tx][r];
}

// ---------------- K1: per-row norms + positive term ----------------
__global__ void stats_kernel() {
    int warp = threadIdx.x >> 5, lane = threadIdx.x & 31;
    int row = blockIdx.x * 8 + warp;
    const float4* r1 = (const float4*)(g_x1t + (size_t)row * DDIM);
    const float4* r2 = (const float4*)(g_x2t + (size_t)row * DDIM);
    float4 a = r1[lane], b = r2[lane];                 // 32 lanes x 4 = 128
    float s1 = a.x*a.x + a.y*a.y + a.z*a.z + a.w*a.w;
    float s2 = b.x*b.x + b.y*b.y + b.z*b.z + b.w*b.w;
    #pragma unroll
    for (int o = 16; o > 0; o >>= 1) {
        s1 += __shfl_xor_sync(0xffffffffu, s1, o);
        s2 += __shfl_xor_sync(0xffffffffu, s2, o);
    }
    float in1 = 1.0f / fmaxf(sqrtf(s1), 1e-12f);
    float in2 = 1.0f / fmaxf(sqrtf(s2), 1e-12f);
    float sc = in1 * in2 * INV_TEMP;
    float p = expf(a.x*b.x*sc) + expf(a.y*b.y*sc) + expf(a.z*b.z*sc) + expf(a.w*b.w*sc);
    #pragma unroll
    for (int o = 16; o > 0; o >>= 1) p += __shfl_xor_sync(0xffffffffu, p, o);
    if (lane == 0) { g_sq[row] = s1; g_invn[row] = in1; g_pos[row] = p; }
}

// ---------------- K2: Gram matrix C = A * A^T (fp32 SIMT SGEMM) ----------------
__global__ __launch_bounds__(256) void gemm_kernel() {
    __shared__ float As[16][132];
    __shared__ float Bs[16][132];
    const float* A = g_x1t;
    int bm = blockIdx.y * 128, bn = blockIdx.x * 128;
    int tid = threadIdx.x;
    int tm = tid >> 4, tn = tid & 15;                  // 16 x 16 thread grid, 8x8 each
    float c[8][8];
    #pragma unroll
    for (int i = 0; i < 8; i++)
        #pragma unroll
        for (int j = 0; j < 8; j++) c[i][j] = 0.0f;

    for (int k0 = 0; k0 < DDIM; k0 += 16) {
        #pragma unroll
        for (int l = 0; l < 2; l++) {
            int idx = tid * 2 + l;                     // 0..511
            int m  = idx >> 2;                         // row within tile
            int kq = (idx & 3) << 2;                   // k-offset (float4)
            float4 va = *(const float4*)(A + (size_t)(bm + m) * DDIM + k0 + kq);
            As[kq+0][m] = va.x; As[kq+1][m] = va.y; As[kq+2][m] = va.z; As[kq+3][m] = va.w;
            float4 vb = *(const float4*)(A + (size_t)(bn + m) * DDIM + k0 + kq);
            Bs[kq+0][m] = vb.x; Bs[kq+1][m] = vb.y; Bs[kq+2][m] = vb.z; Bs[kq+3][m] = vb.w;
        }
        __syncthreads();
        #pragma unroll
        for (int kk = 0; kk < 16; kk++) {
            float a[8], b[8];
            *(float4*)&a[0] = *(const float4*)&As[kk][tm * 8];
            *(float4*)&a[4] = *(const float4*)&As[kk][tm * 8 + 4];
            *(float4*)&b[0] = *(const float4*)&Bs[kk][tn * 8];
            *(float4*)&b[4] = *(const float4*)&Bs[kk][tn * 8 + 4];
            #pragma unroll
            for (int i = 0; i < 8; i++)
                #pragma unroll
                for (int j = 0; j < 8; j++) c[i][j] += a[i] * b[j];
        }
        __syncthreads();
    }
    #pragma unroll
    for (int i = 0; i < 8; i++) {
        size_t row = (size_t)(bm + tm * 8 + i);
        float4* p = (float4*)(g_dot + row * NROWS + bn + tn * 8);
        p[0] = make_float4(c[i][0], c[i][1], c[i][2], c[i][3]);
        p[1] = make_float4(c[i][4], c[i][5], c[i][6], c[i][7]);
    }
}

// ---------------- K3: per-row exact top-100 select + negative sum ----------------
// key_j = |x_j|^2 - 2*dot(i,j)  (d2 minus the per-row constant |x_i|^2; same ranking)
// 100th-largest found by exact 32-step bisection on order-preserving uint bits.
__global__ __launch_bounds__(256) void select_kernel() {
    int i = blockIdx.x;
    int tid = threadIdx.x, lane = tid & 31, warp = tid >> 5;
    const float* drow = g_dot + (size_t)i * NROWS;

    unsigned key[32];
    #pragma unroll
    for (int l = 0; l < 32; l++) {
        int j = tid + l * 256;
        float k = g_sq[j] - 2.0f * drow[j];
        unsigned u = __float_as_uint(k);
        key[l] = (u & 0x80000000u) ? ~u : (u | 0x80000000u);  // total order as uint
    }

    __shared__ unsigned swarp[8];
    __shared__ unsigned scnt;
    unsigned lo = 0u, hi = 0xFFFFFFFFu;
    // invariant: count(key >= lo) >= 100, count(key >= hi+1) < 100
    for (int it = 0; it < 32; it++) {
        unsigned span = hi - lo;
        unsigned mid = lo + (span >> 1) + (span & 1u);
        int c = 0;
        #pragma unroll
        for (int l = 0; l < 32; l++) c += (key[l] >= mid);
        #pragma unroll
        for (int o = 16; o > 0; o >>= 1) c += __shfl_xor_sync(0xffffffffu, c, o);
        if (lane == 0) swarp[warp] = (unsigned)c;
        __syncthreads();
        if (tid == 0) {
            unsigned t = 0;
            for (int w = 0; w < 8; w++) t += swarp[w];
            scnt = t;
        }
        __syncthreads();
        unsigned cnt = scnt;
        if (cnt >= KNEG) lo = mid; else hi = mid - 1u;
    }
    unsigned thr = lo;   // exact bits of the 100th-largest key

    float inv_i = g_invn[i];
    float acc = 0.0f;
    #pragma unroll
    for (int l = 0; l < 32; l++) {
        if (key[l] >= thr) {
            int j = tid + l * 256;
            float d = drow[j];                               // raw dot(i,j)
            acc += expf(d * inv_i * g_invn[j] * INV_TEMP);
        }
    }
    #pragma unroll
    for (int o = 16; o > 0; o >>= 1) acc += __shfl_xor_sync(0xffffffffu, acc, o);
    __shared__ float sacc[8];
    if (lane == 0) sacc[warp] = acc;
    __syncthreads();
    if (tid == 0) {
        float t = 0.0f;
        for (int w = 0; w < 8; w++) t += sacc[w];
        g_loss[i] = log1pf(t / g_pos[i]);    // log(P+N) - log(P)
    }
}

// ---------------- K4: deterministic mean ----------------
__global__ void reduce_kernel(float* __restrict__ out) {
    __shared__ float s[256];
    float a = 0.0f;
    for (int j = threadIdx.x; j < NROWS; j += 256) a += g_loss[j];
    s[threadIdx.x] = a;
    __syncthreads();
    for (int st = 128; st > 0; st >>= 1) {
        if (threadIdx.x < st) s[threadIdx.x] += s[threadIdx.x + st];
        __syncthreads();
    }
    if (threadIdx.x == 0) out[0] = s[0] * (1.0f / NROWS);
}

// ---------------- launch ----------------
extern "C" void kernel_launch(void* const* d_in, const int* in_sizes, int n_in,
                              void* d_out, int out_size) {
    const float* x1 = (const float*)d_in[0];
    const float* x2 = (const float*)d_in[1];
    float* out = (float*)d_out;

    dim3 tgrid(32, 4, 8), tblk(32, 8);
    transpose_kernel<<<tgrid, tblk>>>(x1, 0);
    transpose_kernel<<<tgrid, tblk>>>(x2, 1);
    stats_kernel<<<NROWS / 8, 256>>>();
    gemm_kernel<<<dim3(64, 64), 256>>>();
    select_kernel<<<NROWS, 256>>>();
    reduce_kernel<<<1, 256>>>(out);
}